// round 1
// baseline (speedup 1.0000x reference)
#include <cuda_runtime.h>
#include <cuda_bf16.h>

#define NPATCH   8192
#define P        41
#define PPB      2           // patches per block
#define TPP      48          // threads per patch (41 active in main loop)
#define NSLOT    11          // angular slots for floor(o) in [3,13]
#define CPAD     48          // column stride (bank-conflict friendly: 48 mod 32 = 16)

// ---------------------------------------------------------------------------
// Kernel 1: per-patch gradient/orientation binning + separable spatial pooling.
// Writes UN-normalized 128-d descriptors to out[p*128 + (ang*16 + yb*4 + xb)].
// ---------------------------------------------------------------------------
__global__ __launch_bounds__(PPB * TPP, 6)
void sift_main_kernel(const float* __restrict__ x,
                      const float* __restrict__ gk,
                      float* __restrict__ out)
{
    __shared__ float cs[PPB][4][NSLOT][CPAD];

    const int tid = threadIdx.x;

    // zero accumulators
    {
        float* csf = &cs[0][0][0][0];
        #pragma unroll 4
        for (int k = tid; k < PPB * 4 * NSLOT * CPAD; k += PPB * TPP)
            csf[k] = 0.0f;
    }
    __syncthreads();

    const int pl = tid / TPP;      // patch-in-block
    const int c  = tid % TPP;      // column id (active if < 41)
    const int gp = blockIdx.x * PPB + pl;

    if (c < P) {
        const float* xp = x + (size_t)gp * (P * P);
        const int cm1 = (c > 0)     ? c - 1 : 0;
        const int cp1 = (c < P - 1) ? c + 1 : P - 1;
        const float* pm = xp + cm1;
        const float* pc = xp + c;
        const float* pp = xp + cp1;
        const float* pg = gk + c;

        float* pbase = &cs[pl][0][0][c];   // element (b,s): pbase[(b*NSLOT+s)*CPAD]

        // rolling 3x3 window (only the 7 values actually needed)
        float cur_m1 = __ldg(pm);
        float cur_c  = __ldg(pc);
        float cur_p1 = __ldg(pp);
        float prev_c = cur_c;              // replicate-pad top edge

        #pragma unroll
        for (int y = 0; y < P; ++y) {
            const int yn = (y < P - 1) ? (y + 1) : (P - 1);   // replicate-pad bottom
            const float nxt_m1 = __ldg(pm + yn * P);
            const float nxt_c  = __ldg(pc + yn * P);
            const float nxt_p1 = __ldg(pp + yn * P);

            const float gxv = cur_p1 - cur_m1;
            const float gyv = nxt_c  - prev_c;
            const float gw  = __ldg(pg + y * P);

            // gaussian-weighted magnitude: sqrt(gx^2+gy^2+1e-10) * gk
            const float m2  = fmaf(gyv, gyv, fmaf(gxv, gxv, 1e-10f));
            const float mag = m2 * rsqrtf(m2) * gw;

            // angle -> o = atan2(gy, gx+1e-10)*(4/pi) + 8, o in [~4, ~12]
            const float gxe = gxv + 1e-10f;
            const float ax = fabsf(gxe), ay = fabsf(gyv);
            const float mn = fminf(ax, ay);
            const float mx = fmaxf(fmaxf(ax, ay), 1e-30f);
            const float q  = __fdividef(mn, mx);          // MUFU.RCP + FMUL
            const float s  = q * q;
            // minimax atan(q)*(4/pi) on [0,1], max err ~3e-6
            const float rb = q * fmaf(s, fmaf(s, fmaf(s, fmaf(s,
                                fmaf(s, -0.01492388f, 0.06704029f),
                                -0.14824694f), 0.24642712f), -0.42350938f),
                                1.27321060f);
            const float t1 = (ay > ax)      ? (2.0f - rb) : rb;
            const float t2 = (gxe < 0.0f)   ? (4.0f - t1) : t1;
            const float o  = 8.0f + copysignf(t2, gyv);

            const int   i   = __float2int_rd(o);          // floor, i in [3,12]
            const float wo1 = o - (float)i;
            const float c1v = wo1 * mag;                  // -> slot i+1
            const float c0v = mag - c1v;                  // -> slot i

            float* ap = pbase + (i - 3) * CPAD;

            // y pooling: triangular weights, compile-time constants per y
            #pragma unroll
            for (int b = 0; b < 4; ++b) {
                const int u = y + 4 - 10 * b;
                if (u >= 0 && u <= 15) {
                    const float wy = 8.0f - fabsf((float)u - 7.5f);
                    ap[b * NSLOT * CPAD]        += wy * c0v;
                    ap[b * NSLOT * CPAD + CPAD] += wy * c1v;
                }
            }

            prev_c = cur_c;
            cur_m1 = nxt_m1; cur_c = nxt_c; cur_p1 = nxt_p1;
        }
    }
    __syncthreads();

    // x-fold reduction: out[a][yb][xb] = (1/64) * sum_c wx(c,xb) * colsum
    // angular slot fold: ang a <- slots {i : i%8==a, i in [3,13]}
    #pragma unroll
    for (int r = 0; r < 3; ++r) {
        const int o = c + r * TPP;
        if (o < 128) {
            const int a  = o >> 4;
            const int yb = (o >> 2) & 3;
            const int xb = o & 3;
            const int s1 = (a >= 3) ? (a - 3) : (a + 5);
            const int s2 = (a >= 3 && a <= 5) ? (a + 5) : -1;
            const int cstart = 10 * xb - 4;
            float sum = 0.0f;
            #pragma unroll
            for (int dc = 0; dc < 16; ++dc) {
                const int cc = cstart + dc;
                if (cc >= 0 && cc < P) {
                    const float wx = 8.0f - fabsf((float)dc - 7.5f);
                    float v = cs[pl][yb][s1][cc];
                    if (s2 >= 0) v += cs[pl][yb][s2][cc];
                    sum = fmaf(wx, v, sum);
                }
            }
            out[(size_t)gp * 128 + o] = sum * 0.015625f;   // 1/64
        }
    }
}

// ---------------------------------------------------------------------------
// Kernel 2: in-place normalization, one warp per patch.
// L2-normalize -> clip 0.2 -> L2-normalize -> L1-normalize -> sqrt(+1e-10)
// ---------------------------------------------------------------------------
__global__ __launch_bounds__(256)
void sift_norm_kernel(float* __restrict__ out)
{
    const int warp = threadIdx.x >> 5;
    const int lane = threadIdx.x & 31;
    const int p = blockIdx.x * (blockDim.x >> 5) + warp;
    if (p >= NPATCH) return;

    float* d = out + (size_t)p * 128;
    float v0 = d[lane];
    float v1 = d[lane + 32];
    float v2 = d[lane + 64];
    float v3 = d[lane + 96];

    // L2 normalize
    float ss = v0 * v0 + v1 * v1 + v2 * v2 + v3 * v3;
    #pragma unroll
    for (int k = 16; k; k >>= 1) ss += __shfl_xor_sync(0xffffffffu, ss, k);
    float inv = 1.0f / fmaxf(sqrtf(ss), 1e-12f);
    v0 *= inv; v1 *= inv; v2 *= inv; v3 *= inv;

    // clip [0, 0.2]
    v0 = fminf(fmaxf(v0, 0.0f), 0.2f);
    v1 = fminf(fmaxf(v1, 0.0f), 0.2f);
    v2 = fminf(fmaxf(v2, 0.0f), 0.2f);
    v3 = fminf(fmaxf(v3, 0.0f), 0.2f);

    // L2 normalize again
    float ss2 = v0 * v0 + v1 * v1 + v2 * v2 + v3 * v3;
    #pragma unroll
    for (int k = 16; k; k >>= 1) ss2 += __shfl_xor_sync(0xffffffffu, ss2, k);
    float inv2 = 1.0f / fmaxf(sqrtf(ss2), 1e-12f);
    v0 *= inv2; v1 *= inv2; v2 *= inv2; v3 *= inv2;

    // L1 normalize + rootsift
    float l1 = fabsf(v0) + fabsf(v1) + fabsf(v2) + fabsf(v3);
    #pragma unroll
    for (int k = 16; k; k >>= 1) l1 += __shfl_xor_sync(0xffffffffu, l1, k);
    float inv3 = 1.0f / fmaxf(l1, 1e-12f);

    d[lane]      = sqrtf(fmaf(v0, inv3, 1e-10f));
    d[lane + 32] = sqrtf(fmaf(v1, inv3, 1e-10f));
    d[lane + 64] = sqrtf(fmaf(v2, inv3, 1e-10f));
    d[lane + 96] = sqrtf(fmaf(v3, inv3, 1e-10f));
}

// ---------------------------------------------------------------------------
extern "C" void kernel_launch(void* const* d_in, const int* in_sizes, int n_in,
                              void* d_out, int out_size)
{
    const float* x  = nullptr;
    const float* gk = nullptr;
    for (int i = 0; i < n_in; ++i) {
        if (in_sizes[i] == NPATCH * P * P) x  = (const float*)d_in[i];
        else if (in_sizes[i] == P * P)     gk = (const float*)d_in[i];
        // pk (256 elems) unused: pooling weights are exact dyadic rationals,
        // recomputed analytically as compile-time constants.
    }
    float* out = (float*)d_out;

    sift_main_kernel<<<NPATCH / PPB, PPB * TPP>>>(x, gk, out);
    sift_norm_kernel<<<(NPATCH + 7) / 8, 256>>>(out);
}

// round 2
// speedup vs baseline: 1.0056x; 1.0056x over previous
#include <cuda_runtime.h>
#include <cuda_bf16.h>

#define NPATCH   8192
#define P        41
#define PPB      2           // patches per block
#define TPP      48          // threads per patch (41 active in main loop)
#define NSLOT    11          // angular slots for floor(o) in [3,13]
#define CPAD     48          // column stride (bank-conflict friendly: 48 mod 32 = 16)

// ---------------------------------------------------------------------------
// Single fused kernel: gradient/orientation binning + separable spatial
// pooling + full normalization chain. Writes final descriptors to out.
// ---------------------------------------------------------------------------
__global__ __launch_bounds__(PPB * TPP, 6)
void sift_fused_kernel(const float* __restrict__ x,
                       const float* __restrict__ gk,
                       float* __restrict__ out)
{
    __shared__ float cs[PPB][4][NSLOT][CPAD];
    __shared__ float sdesc[PPB][128];

    const int tid = threadIdx.x;

    // zero accumulators
    {
        float* csf = &cs[0][0][0][0];
        #pragma unroll 4
        for (int k = tid; k < PPB * 4 * NSLOT * CPAD; k += PPB * TPP)
            csf[k] = 0.0f;
    }
    __syncthreads();

    const int pl = tid / TPP;      // patch-in-block
    const int c  = tid % TPP;      // column id (active if < 41)
    const int gp = blockIdx.x * PPB + pl;

    if (c < P) {
        const float* xp = x + (size_t)gp * (P * P);
        const int cm1 = (c > 0)     ? c - 1 : 0;
        const int cp1 = (c < P - 1) ? c + 1 : P - 1;
        const float* pm = xp + cm1;
        const float* pc = xp + c;
        const float* pp = xp + cp1;
        const float* pg = gk + c;

        float* pbase = &cs[pl][0][0][c];   // element (b,s): pbase[(b*NSLOT+s)*CPAD]

        // rolling 3x3 window (only the 7 values actually needed)
        float cur_m1 = __ldg(pm);
        float cur_c  = __ldg(pc);
        float cur_p1 = __ldg(pp);
        float prev_c = cur_c;              // replicate-pad top edge

        #pragma unroll
        for (int y = 0; y < P; ++y) {
            const int yn = (y < P - 1) ? (y + 1) : (P - 1);   // replicate-pad bottom
            const float nxt_m1 = __ldg(pm + yn * P);
            const float nxt_c  = __ldg(pc + yn * P);
            const float nxt_p1 = __ldg(pp + yn * P);

            const float gxv = cur_p1 - cur_m1;
            const float gyv = nxt_c  - prev_c;
            const float gw  = __ldg(pg + y * P);

            // gaussian-weighted magnitude: sqrt(gx^2+gy^2+1e-10) * gk
            const float m2  = fmaf(gyv, gyv, fmaf(gxv, gxv, 1e-10f));
            const float mag = m2 * rsqrtf(m2) * gw;

            // angle -> o = atan2(gy, gx+1e-10)*(4/pi) + 8, o in [~4, ~12]
            const float gxe = gxv + 1e-10f;
            const float ax = fabsf(gxe), ay = fabsf(gyv);
            const float mn = fminf(ax, ay);
            const float mx = fmaxf(fmaxf(ax, ay), 1e-30f);
            const float q  = __fdividef(mn, mx);          // MUFU.RCP + FMUL
            const float s  = q * q;
            // minimax atan(q)*(4/pi) on [0,1], max err ~3e-6
            const float rb = q * fmaf(s, fmaf(s, fmaf(s, fmaf(s,
                                fmaf(s, -0.01492388f, 0.06704029f),
                                -0.14824694f), 0.24642712f), -0.42350938f),
                                1.27321060f);
            const float t1 = (ay > ax)      ? (2.0f - rb) : rb;
            const float t2 = (gxe < 0.0f)   ? (4.0f - t1) : t1;
            const float o  = 8.0f + copysignf(t2, gyv);

            const int   i   = __float2int_rd(o);          // floor, i in [3,12]
            const float wo1 = o - (float)i;
            const float c1v = wo1 * mag;                  // -> slot i+1
            const float c0v = mag - c1v;                  // -> slot i

            float* ap = pbase + (i - 3) * CPAD;

            // y pooling: triangular weights, compile-time constants per y
            #pragma unroll
            for (int b = 0; b < 4; ++b) {
                const int u = y + 4 - 10 * b;
                if (u >= 0 && u <= 15) {
                    const float wy = 8.0f - fabsf((float)u - 7.5f);
                    ap[b * NSLOT * CPAD]        += wy * c0v;
                    ap[b * NSLOT * CPAD + CPAD] += wy * c1v;
                }
            }

            prev_c = cur_c;
            cur_m1 = nxt_m1; cur_c = nxt_c; cur_p1 = nxt_p1;
        }
    }
    __syncthreads();

    // x-fold reduction into sdesc: desc[a][yb][xb] = (1/64) * sum_c wx * colsum
    // angular slot fold: ang a <- slots {i : i%8==a, i in [3,13]}
    #pragma unroll
    for (int r = 0; r < 3; ++r) {
        const int o = c + r * TPP;
        if (o < 128) {
            const int a  = o >> 4;
            const int yb = (o >> 2) & 3;
            const int xb = o & 3;
            const int s1 = (a >= 3) ? (a - 3) : (a + 5);
            const int s2 = (a >= 3 && a <= 5) ? (a + 5) : -1;
            const int cstart = 10 * xb - 4;
            float sum = 0.0f;
            #pragma unroll
            for (int dc = 0; dc < 16; ++dc) {
                const int cc = cstart + dc;
                if (cc >= 0 && cc < P) {
                    const float wx = 8.0f - fabsf((float)dc - 7.5f);
                    float v = cs[pl][yb][s1][cc];
                    if (s2 >= 0) v += cs[pl][yb][s2][cc];
                    sum = fmaf(wx, v, sum);
                }
            }
            sdesc[pl][o] = sum * 0.015625f;   // 1/64
        }
    }
    __syncthreads();

    // ---- fused normalization: warp 0 -> patch 0, warp 2 -> patch 1 ----
    // L2-normalize -> clip 0.2 -> L2-normalize -> L1-normalize -> sqrt(+1e-10)
    const int warp = tid >> 5;
    if ((warp & 1) == 0) {
        const int pw   = warp >> 1;            // 0 or 1
        const int lane = tid & 31;
        const float* sd = sdesc[pw];

        float v0 = sd[lane];
        float v1 = sd[lane + 32];
        float v2 = sd[lane + 64];
        float v3 = sd[lane + 96];

        float ss = v0 * v0 + v1 * v1 + v2 * v2 + v3 * v3;
        #pragma unroll
        for (int k = 16; k; k >>= 1) ss += __shfl_xor_sync(0xffffffffu, ss, k);
        float inv = 1.0f / fmaxf(sqrtf(ss), 1e-12f);
        v0 *= inv; v1 *= inv; v2 *= inv; v3 *= inv;

        v0 = fminf(fmaxf(v0, 0.0f), 0.2f);
        v1 = fminf(fmaxf(v1, 0.0f), 0.2f);
        v2 = fminf(fmaxf(v2, 0.0f), 0.2f);
        v3 = fminf(fmaxf(v3, 0.0f), 0.2f);

        float ss2 = v0 * v0 + v1 * v1 + v2 * v2 + v3 * v3;
        #pragma unroll
        for (int k = 16; k; k >>= 1) ss2 += __shfl_xor_sync(0xffffffffu, ss2, k);
        float inv2 = 1.0f / fmaxf(sqrtf(ss2), 1e-12f);
        v0 *= inv2; v1 *= inv2; v2 *= inv2; v3 *= inv2;

        float l1 = fabsf(v0) + fabsf(v1) + fabsf(v2) + fabsf(v3);
        #pragma unroll
        for (int k = 16; k; k >>= 1) l1 += __shfl_xor_sync(0xffffffffu, l1, k);
        float inv3 = 1.0f / fmaxf(l1, 1e-12f);

        float* d = out + (size_t)(blockIdx.x * PPB + pw) * 128;
        d[lane]      = sqrtf(fmaf(v0, inv3, 1e-10f));
        d[lane + 32] = sqrtf(fmaf(v1, inv3, 1e-10f));
        d[lane + 64] = sqrtf(fmaf(v2, inv3, 1e-10f));
        d[lane + 96] = sqrtf(fmaf(v3, inv3, 1e-10f));
    }
}

// ---------------------------------------------------------------------------
extern "C" void kernel_launch(void* const* d_in, const int* in_sizes, int n_in,
                              void* d_out, int out_size)
{
    const float* x  = nullptr;
    const float* gk = nullptr;
    for (int i = 0; i < n_in; ++i) {
        if (in_sizes[i] == NPATCH * P * P) x  = (const float*)d_in[i];
        else if (in_sizes[i] == P * P)     gk = (const float*)d_in[i];
        // pk (256 elems) unused: pooling weights are exact dyadic rationals,
        // recomputed analytically as compile-time constants.
    }
    float* out = (float*)d_out;

    sift_fused_kernel<<<NPATCH / PPB, PPB * TPP>>>(x, gk, out);
}